// round 3
// baseline (speedup 1.0000x reference)
#include <cuda_runtime.h>
#include <cstdint>

// Max-unpooling 2x2 stride 2, (32,64,112,112) -> (32,64,224,224).
// Non-overlapping windows => pure gather/expand, no atomics, no zero pass.
// 8 input pixels per thread: warp reads 2KB contiguous, writes two 2KB
// contiguous row streams. Streaming hints (no reuse anywhere).

static constexpr int H_IN   = 112;
static constexpr int W_IN   = 112;
static constexpr int W_OUT  = 224;
static constexpr int HW_IN  = H_IN * W_IN;      // 12544
static constexpr int HW_OUT = W_OUT * W_OUT;    // 50176

__global__ void __launch_bounds__(256) unpool_kernel8(
    const float* __restrict__ fm,
    const int*   __restrict__ sw,
    float*       __restrict__ out,
    int total8)
{
    int t = blockIdx.x * blockDim.x + threadIdx.x;
    if (t >= total8) return;

    int idx = t * 8;                 // first input pixel index (8 per thread)
    int bc  = idx / HW_IN;
    int rem = idx - bc * HW_IN;
    int h   = rem / W_IN;
    int w   = rem - h * W_IN;        // multiple of 8 (112 % 8 == 0)

    const float4* fm4 = reinterpret_cast<const float4*>(fm);
    const int4*   sw4 = reinterpret_cast<const int4*>(sw);

    size_t obase = (size_t)bc * HW_OUT + (size_t)(2 * h) * W_OUT + 2 * w;
    float4* orow0 = reinterpret_cast<float4*>(out + obase);
    float4* orow1 = reinterpret_cast<float4*>(out + obase + W_OUT);

#pragma unroll
    for (int q = 0; q < 2; q++) {
        float4 v = __ldcs(&fm4[2 * t + q]);
        int4   s = __ldcs(&sw4[2 * t + q]);

        // input pixel j (value vj, switch sj) maps within its 2x2 window:
        //   top row (2h):     col offset sj      if sj < 2
        //   bottom row (2h+1):col offset sj - 2  if sj >= 2
        float4 top0, top1, bot0, bot1;
        top0.x = (s.x == 0) ? v.x : 0.0f;
        top0.y = (s.x == 1) ? v.x : 0.0f;
        top0.z = (s.y == 0) ? v.y : 0.0f;
        top0.w = (s.y == 1) ? v.y : 0.0f;
        top1.x = (s.z == 0) ? v.z : 0.0f;
        top1.y = (s.z == 1) ? v.z : 0.0f;
        top1.z = (s.w == 0) ? v.w : 0.0f;
        top1.w = (s.w == 1) ? v.w : 0.0f;

        bot0.x = (s.x == 2) ? v.x : 0.0f;
        bot0.y = (s.x == 3) ? v.x : 0.0f;
        bot0.z = (s.y == 2) ? v.y : 0.0f;
        bot0.w = (s.y == 3) ? v.y : 0.0f;
        bot1.x = (s.z == 2) ? v.z : 0.0f;
        bot1.y = (s.z == 3) ? v.z : 0.0f;
        bot1.z = (s.w == 2) ? v.w : 0.0f;
        bot1.w = (s.w == 3) ? v.w : 0.0f;

        __stcs(&orow0[2 * q + 0], top0);
        __stcs(&orow0[2 * q + 1], top1);
        __stcs(&orow1[2 * q + 0], bot0);
        __stcs(&orow1[2 * q + 1], bot1);
    }
}

extern "C" void kernel_launch(void* const* d_in, const int* in_sizes, int n_in,
                              void* d_out, int out_size)
{
    const float* fm = (const float*)d_in[0];
    const int*   sw = (const int*)d_in[1];
    float*       out = (float*)d_out;

    int total  = in_sizes[0];            // 32*64*112*112 = 25690112
    int total8 = (total + 7) / 8;        // 3211264 (exactly divisible)
    int threads = 256;
    int blocks  = (total8 + threads - 1) / threads;  // 12544
    unpool_kernel8<<<blocks, threads>>>(fm, sw, out, total8);
}

// round 4
// speedup vs baseline: 1.4204x; 1.4204x over previous
#include <cuda_runtime.h>
#include <cstdint>

// Max-unpooling 2x2 stride 2, (32,64,112,112) -> (32,64,224,224).
// Non-overlapping windows => pure gather/expand, no atomics, no zero pass.
// One thread per 2 input pixels: float2/int2 coalesced load, two float4
// stores (top row, bottom row) that are lane-contiguous across the warp
// => every STG.128 writes full 128B lines (512B contiguous per warp).

static constexpr int H_IN   = 112;
static constexpr int W_IN   = 112;
static constexpr int W_OUT  = 224;
static constexpr int HW_IN  = H_IN * W_IN;      // 12544
static constexpr int HW_OUT = W_OUT * W_OUT;    // 50176

__global__ void __launch_bounds__(256) unpool_kernel2(
    const float* __restrict__ fm,
    const int*   __restrict__ sw,
    float*       __restrict__ out,
    int total2)
{
    int t = blockIdx.x * blockDim.x + threadIdx.x;
    if (t >= total2) return;

    int idx = t * 2;                 // first of this thread's 2 input pixels
    int bc  = idx / HW_IN;
    int rem = idx - bc * HW_IN;
    int h   = rem / W_IN;
    int w   = rem - h * W_IN;        // even

    float2 v = reinterpret_cast<const float2*>(fm)[t];
    int2   s = reinterpret_cast<const int2*>(sw)[t];

    // pixel j (value vj, switch sj), window at output (2h, 2(w+j)):
    //   top row:    col offset sj       if sj < 2
    //   bottom row: col offset sj - 2   if sj >= 2
    float4 top, bot;
    top.x = (s.x == 0) ? v.x : 0.0f;
    top.y = (s.x == 1) ? v.x : 0.0f;
    top.z = (s.y == 0) ? v.y : 0.0f;
    top.w = (s.y == 1) ? v.y : 0.0f;

    bot.x = (s.x == 2) ? v.x : 0.0f;
    bot.y = (s.x == 3) ? v.x : 0.0f;
    bot.z = (s.y == 2) ? v.y : 0.0f;
    bot.w = (s.y == 3) ? v.y : 0.0f;

    size_t obase = (size_t)bc * HW_OUT + (size_t)(2 * h) * W_OUT + 2 * w;
    *reinterpret_cast<float4*>(out + obase)         = top;   // row 2h
    *reinterpret_cast<float4*>(out + obase + W_OUT) = bot;   // row 2h+1
}

extern "C" void kernel_launch(void* const* d_in, const int* in_sizes, int n_in,
                              void* d_out, int out_size)
{
    const float* fm = (const float*)d_in[0];
    const int*   sw = (const int*)d_in[1];
    float*       out = (float*)d_out;

    int total  = in_sizes[0];            // 32*64*112*112 = 25690112
    int total2 = (total + 1) / 2;        // 12845056
    int threads = 256;
    int blocks  = (total2 + threads - 1) / threads;  // 50176
    unpool_kernel2<<<blocks, threads>>>(fm, sw, out, total2);
}